// round 9
// baseline (speedup 1.0000x reference)
#include <cuda_runtime.h>
#include <cuda_fp16.h>
#include <cstdint>

// ---------------------------------------------------------------------------
// BitLinear via 2-level int8 IMMA:
//   x ~= s1[m] * (xh + xl/128),  xh,xl int8 (|xh|<=127, |xl|<=64)
//   w  = ternary int8 {-1,0,1},  wscale[n]
//   out[m,n] = wscale[n]*s1[m]/128 * (128*dot(xh,w) + dot(xl,w))   (s32 exact)
//
// GEMM: mma.sync.m16n8k32.s32.s8.s8.s32, CTA 128x128, 4 warps (64x64 each),
// BK=64 (2 k-steps of 32), 3-stage cp.async, 2 CTAs/SM. Two K-passes (hi, lo)
// reusing one s32 accumulator; hi partial parked in out[] (CTA-local RMW).
// Tests whether the sm_103 legacy-tensor floor is per-instruction (-> ~2x)
// or per-MAC (-> parity).
// ---------------------------------------------------------------------------

#define M_TOT 8192
#define N_TOT 8192
#define K_TOT 2048

#define BM 128
#define BN 128
#define BK 64
#define NUM_CHUNKS (K_TOT / BK)      // 32

// int8 tiles: row = 64 data + 16 pad = 80 bytes (5 x 16B granules, odd)
#define T8ROWB 80
#define TILE8_BYTES (128 * T8ROWB)   // 10240
#define STAGE_BYTES (2 * TILE8_BYTES)             // A + B per stage
#define SMEM_A_OFF(s) ((s) * STAGE_BYTES)
#define SMEM_B_OFF(s) ((s) * STAGE_BYTES + TILE8_BYTES)
#define SMEM_TOTAL (3 * STAGE_BYTES)              // 61440

__device__ int8_t g_Xh8[(size_t)M_TOT * K_TOT];
__device__ int8_t g_Xl8[(size_t)M_TOT * K_TOT];
__device__ int8_t g_Wq [(size_t)N_TOT * K_TOT];
__device__ float  g_s1 [M_TOT];
__device__ float  g_scale[N_TOT];

// ------------------------------ helpers ------------------------------------
__device__ __forceinline__ uint32_t smem_u32(const void* p) {
    uint32_t a;
    asm("{ .reg .u64 t; cvta.to.shared.u64 t, %1; cvt.u32.u64 %0, t; }"
        : "=r"(a) : "l"(p));
    return a;
}

__device__ __forceinline__ void cp_async16(uint32_t dst, const void* src) {
    asm volatile("cp.async.cg.shared.global [%0], [%1], 16;"
                 :: "r"(dst), "l"(src));
}

__device__ __forceinline__ void ldsm_x4(uint32_t addr, uint32_t* r) {
    asm volatile("ldmatrix.sync.aligned.m8n8.x4.shared.b16 {%0,%1,%2,%3}, [%4];"
                 : "=r"(r[0]), "=r"(r[1]), "=r"(r[2]), "=r"(r[3]) : "r"(addr));
}

__device__ __forceinline__ void imma16832(int* c, const uint32_t* a,
                                          uint32_t b0, uint32_t b1) {
    asm volatile(
        "mma.sync.aligned.m16n8k32.row.col.s32.s8.s8.s32 "
        "{%0,%1,%2,%3}, {%4,%5,%6,%7}, {%8,%9}, {%0,%1,%2,%3};"
        : "+r"(c[0]), "+r"(c[1]), "+r"(c[2]), "+r"(c[3])
        : "r"(a[0]), "r"(a[1]), "r"(a[2]), "r"(a[3]), "r"(b0), "r"(b1));
}

// ------------------------------ prep kernels -------------------------------
// x -> xh, xl (2-level int8) + per-row scale s1
__global__ void convert_x_kernel(const float* __restrict__ x) {
    const int row = blockIdx.x;
    const int tid = threadIdx.x;
    const float* xr = x + (size_t)row * K_TOT;

    const int base = tid * 8;                    // 256 * 8 = 2048
    float4 a = *reinterpret_cast<const float4*>(xr + base);
    float4 b = *reinterpret_cast<const float4*>(xr + base + 4);
    float v[8] = {a.x, a.y, a.z, a.w, b.x, b.y, b.z, b.w};

    float mx = 0.f;
    #pragma unroll
    for (int i = 0; i < 8; i++) mx = fmaxf(mx, fabsf(v[i]));
    #pragma unroll
    for (int o = 16; o; o >>= 1)
        mx = fmaxf(mx, __shfl_xor_sync(0xFFFFFFFFu, mx, o));

    __shared__ float warp_m[8];
    __shared__ float s_s1;
    if ((tid & 31) == 0) warp_m[tid >> 5] = mx;
    __syncthreads();
    if (tid == 0) {
        float t = warp_m[0];
        #pragma unroll
        for (int i = 1; i < 8; i++) t = fmaxf(t, warp_m[i]);
        float s1 = fmaxf(t, 1e-30f) * (1.0f / 127.0f);
        g_s1[row] = s1;
        s_s1 = s1;
    }
    __syncthreads();
    const float s1 = s_s1;
    const float inv1 = 1.0f / s1;

    int8_t qh[8], ql[8];
    #pragma unroll
    for (int i = 0; i < 8; i++) {
        float h = rintf(v[i] * inv1);
        h = fmaxf(-127.f, fminf(127.f, h));
        float r = v[i] - s1 * h;
        float l = rintf(r * inv1 * 128.0f);
        l = fmaxf(-127.f, fminf(127.f, l));
        qh[i] = (int8_t)(int)h;
        ql[i] = (int8_t)(int)l;
    }
    *reinterpret_cast<uint2*>(g_Xh8 + (size_t)row * K_TOT + base) =
        *reinterpret_cast<uint2*>(qh);
    *reinterpret_cast<uint2*>(g_Xl8 + (size_t)row * K_TOT + base) =
        *reinterpret_cast<uint2*>(ql);
}

__global__ void quantize_w_kernel(const float* __restrict__ W) {
    const int row = blockIdx.x;
    const int tid = threadIdx.x;
    const float* wr = W + (size_t)row * K_TOT;

    const int base = tid * 8;
    float4 a = *reinterpret_cast<const float4*>(wr + base);
    float4 b = *reinterpret_cast<const float4*>(wr + base + 4);
    float s = fabsf(a.x) + fabsf(a.y) + fabsf(a.z) + fabsf(a.w) +
              fabsf(b.x) + fabsf(b.y) + fabsf(b.z) + fabsf(b.w);
    #pragma unroll
    for (int o = 16; o; o >>= 1) s += __shfl_xor_sync(0xFFFFFFFFu, s, o);

    __shared__ float warp_s[8];
    __shared__ float s_scale;
    if ((tid & 31) == 0) warp_s[tid >> 5] = s;
    __syncthreads();
    if (tid == 0) {
        float t = 0.f;
        #pragma unroll
        for (int i = 0; i < 8; i++) t += warp_s[i];
        float sc = t * (1.0f / 2048.0f);
        if (sc < 1e-5f) sc = 1e-5f;
        g_scale[row] = sc;
        s_scale = sc;
    }
    __syncthreads();
    const float sc = s_scale;

    float v[8] = {a.x, a.y, a.z, a.w, b.x, b.y, b.z, b.w};
    int8_t q[8];
    #pragma unroll
    for (int i = 0; i < 8; i++) {
        float t = rintf(v[i] / sc);              // matches jnp.round
        t = fmaxf(-1.f, fminf(1.f, t));
        q[i] = (int8_t)(int)t;
    }
    *reinterpret_cast<uint2*>(g_Wq + (size_t)row * K_TOT + base) =
        *reinterpret_cast<uint2*>(q);
}

// ------------------------------ GEMM kernel --------------------------------
__global__ void __launch_bounds__(128, 2)
bitlinear_gemm(float* __restrict__ out) {
    extern __shared__ char smem[];
    const uint32_t sbase = smem_u32(smem);
    const int tid    = threadIdx.x;
    const int wid    = tid >> 5;
    const int lane   = tid & 31;
    const int warp_m = wid & 1;       // 2 warps along M (64 each)
    const int warp_n = wid >> 1;      // 2 warps along N (64 each)
    const int m0 = blockIdx.y * BM;
    const int n0 = blockIdx.x * BN;

    const int8_t* Bg = g_Wq + (size_t)n0 * K_TOT;

    // A/B each: 128 rows x 4 segs(16B) = 512 segs -> 4/thread
    auto issue_copy = [&](const int8_t* Ag, int stage, int chunk) {
        const int k0 = chunk * BK;
        uint32_t da = sbase + SMEM_A_OFF(stage);
        uint32_t db = sbase + SMEM_B_OFF(stage);
        #pragma unroll
        for (int j = 0; j < 4; j++) {
            int s = tid + 128 * j;
            int row = s >> 2, sg = s & 3;
            uint32_t off = row * T8ROWB + sg * 16;
            cp_async16(da + off, Ag + (size_t)row * K_TOT + k0 + sg * 16);
            cp_async16(db + off, Bg + (size_t)row * K_TOT + k0 + sg * 16);
        }
    };

    // ldmatrix address components (int8, 80B rows)
    // A x4: mats = {m0-7,k0},{m8-15,k0},{m0-7,k16},{m8-15,k16}
    const int aRow = warp_m * 64 + (lane & 15);        // + mt*16
    const int aKof = (lane >> 4) * 16;                 // + ks*32
    // B x4: mats = {n0-7,k0},{n0-7,k16},{n8-15,k0},{n8-15,k16} (per n16 pair)
    const int bRow = warp_n * 64 + ((lane >> 4) << 3) + (lane & 7); // + ntp*16
    const int bKof = ((lane >> 3) & 1) * 16;           // + ks*32

    int acc[4][8][4];

    #pragma unroll 1
    for (int pass = 0; pass < 2; pass++) {
        const int8_t* Ag =
            (pass ? g_Xl8 : g_Xh8) + (size_t)m0 * K_TOT;

        #pragma unroll
        for (int i = 0; i < 4; i++)
            #pragma unroll
            for (int j = 0; j < 8; j++)
                #pragma unroll
                for (int t = 0; t < 4; t++) acc[i][j][t] = 0;

        __syncthreads();   // stages free (prev pass fully consumed)

        issue_copy(Ag, 0, 0);
        asm volatile("cp.async.commit_group;");
        issue_copy(Ag, 1, 1);
        asm volatile("cp.async.commit_group;");

        for (int c = 0; c < NUM_CHUNKS; c++) {
            asm volatile("cp.async.wait_group %0;" :: "n"(1));
            __syncthreads();

            const int nc = c + 2;
            if (nc < NUM_CHUNKS) issue_copy(Ag, nc % 3, nc);
            asm volatile("cp.async.commit_group;");

            const int st = c % 3;
            const uint32_t sa = sbase + SMEM_A_OFF(st);
            const uint32_t sb = sbase + SMEM_B_OFF(st);

            #pragma unroll
            for (int ks = 0; ks < 2; ks++) {     // 2 x k32
                uint32_t af[4][4];
                #pragma unroll
                for (int mt = 0; mt < 4; mt++)
                    ldsm_x4(sa + (aRow + mt * 16) * T8ROWB + ks * 32 + aKof,
                            af[mt]);
                uint32_t bf[4][4];               // [ntpair][4]
                #pragma unroll
                for (int ntp = 0; ntp < 4; ntp++)
                    ldsm_x4(sb + (bRow + ntp * 16) * T8ROWB + ks * 32 + bKof,
                            bf[ntp]);
                #pragma unroll
                for (int mi = 0; mi < 4; mi++)
                    #pragma unroll
                    for (int ni = 0; ni < 8; ni++)
                        imma16832(acc[mi][ni], af[mi],
                                  bf[ni >> 1][(ni & 1) * 2],
                                  bf[ni >> 1][(ni & 1) * 2 + 1]);
            }
        }

        // ---------------- per-pass epilogue --------------------------------
        const int q = lane >> 2;      // row-in-8
        const int t = lane & 3;       // col-pair
        if (pass == 0) {
            // park raw hi partials in out[]
            #pragma unroll
            for (int ni = 0; ni < 8; ni++) {
                const int n = n0 + warp_n * 64 + ni * 8 + t * 2;
                #pragma unroll
                for (int mi = 0; mi < 4; mi++) {
                    const int m = m0 + warp_m * 64 + mi * 16 + q;
                    float2 v0 = make_float2((float)acc[mi][ni][0],
                                            (float)acc[mi][ni][1]);
                    float2 v1 = make_float2((float)acc[mi][ni][2],
                                            (float)acc[mi][ni][3]);
                    *reinterpret_cast<float2*>(out + (size_t)m * N_TOT + n) = v0;
                    *reinterpret_cast<float2*>(out + (size_t)(m + 8) * N_TOT + n) = v1;
                }
            }
        } else {
            // merge: out = (hi*128 + lo) * s1[m] * wscale[n] / 128
            #pragma unroll
            for (int ni = 0; ni < 8; ni++) {
                const int n = n0 + warp_n * 64 + ni * 8 + t * 2;
                const float2 wsc = *reinterpret_cast<const float2*>(&g_scale[n]);
                #pragma unroll
                for (int mi = 0; mi < 4; mi++) {
                    const int m = m0 + warp_m * 64 + mi * 16 + q;
                    const float sm0 = g_s1[m] * 0.0078125f;
                    const float sm1 = g_s1[m + 8] * 0.0078125f;
                    float* p0 = out + (size_t)m * N_TOT + n;
                    float* p1 = out + (size_t)(m + 8) * N_TOT + n;
                    float2 h0 = *reinterpret_cast<float2*>(p0);
                    float2 h1 = *reinterpret_cast<float2*>(p1);
                    float2 v0, v1;
                    v0.x = (h0.x * 128.f + (float)acc[mi][ni][0]) * sm0 * wsc.x;
                    v0.y = (h0.y * 128.f + (float)acc[mi][ni][1]) * sm0 * wsc.y;
                    v1.x = (h1.x * 128.f + (float)acc[mi][ni][2]) * sm1 * wsc.x;
                    v1.y = (h1.y * 128.f + (float)acc[mi][ni][3]) * sm1 * wsc.y;
                    *reinterpret_cast<float2*>(p0) = v0;
                    *reinterpret_cast<float2*>(p1) = v1;
                }
            }
        }
    }
}

// ------------------------------ launch -------------------------------------
extern "C" void kernel_launch(void* const* d_in, const int* in_sizes, int n_in,
                              void* d_out, int out_size) {
    const float* x = (const float*)d_in[0];      // [4,2048,2048]
    const float* w = (const float*)d_in[1];      // [8192,2048]
    float* out = (float*)d_out;                  // [4,2048,8192]

    cudaFuncSetAttribute(bitlinear_gemm,
                         cudaFuncAttributeMaxDynamicSharedMemorySize,
                         SMEM_TOTAL);

    convert_x_kernel<<<M_TOT, 256>>>(x);
    quantize_w_kernel<<<N_TOT, 256>>>(w);

    dim3 grid(N_TOT / BN, M_TOT / BM);
    bitlinear_gemm<<<grid, 128, SMEM_TOTAL>>>(out);
}

// round 10
// speedup vs baseline: 4.4714x; 4.4714x over previous
#include <cuda_runtime.h>
#include <cuda_fp16.h>
#include <cstdint>

// ---------------------------------------------------------------------------
// BitLinear: out[m,n] = scale[n] * sum_k xh[m,k] * wq[n,k]
//   xh  = fp16(x)                  [8192, 2048]
//   wq  = ternary {-1,0,1} fp16    [8192, 2048]
//   out = fp32                     [8192, 8192]
//
// mma.sync.m16n8k16 with FP16 accumulators (tests double-rate HMMA.F16),
// promoted to fp32 registers every 2 chunks (K=128 span) for precision.
// CTA 128x128, 8 warps (64x32 each), BK=64, 3 stages, 2 CTAs/SM.
// ---------------------------------------------------------------------------

#define M_TOT 8192
#define N_TOT 8192
#define K_TOT 2048

#define BM 128
#define BN 128
#define BK 64
#define STAGES 3
#define NUM_CHUNKS (K_TOT / BK)      // 32

// smem row: 64 halves + 8 pad = 72 halves = 144 bytes
#define SROWB 144
#define STILE_BYTES (BM * SROWB)     // 18432
#define SMEM_A_OFF(s) ((s) * STILE_BYTES)
#define SMEM_B_OFF(s) (STAGES * STILE_BYTES + (s) * STILE_BYTES)
#define SMEM_TOTAL (2 * STAGES * STILE_BYTES)   // 110592

__device__ __half g_Xh[(size_t)M_TOT * K_TOT];
__device__ __half g_Wq[(size_t)N_TOT * K_TOT];
__device__ float  g_scale[N_TOT];

// ------------------------------ helpers ------------------------------------
__device__ __forceinline__ uint32_t smem_u32(const void* p) {
    uint32_t a;
    asm("{ .reg .u64 t; cvta.to.shared.u64 t, %1; cvt.u32.u64 %0, t; }"
        : "=r"(a) : "l"(p));
    return a;
}

__device__ __forceinline__ void cp_async16(uint32_t dst, const void* src) {
    asm volatile("cp.async.cg.shared.global [%0], [%1], 16;"
                 :: "r"(dst), "l"(src));
}

__device__ __forceinline__ void ldsm_x4(uint32_t addr, uint32_t* r) {
    asm volatile("ldmatrix.sync.aligned.m8n8.x4.shared.b16 {%0,%1,%2,%3}, [%4];"
                 : "=r"(r[0]), "=r"(r[1]), "=r"(r[2]), "=r"(r[3]) : "r"(addr));
}

// fp16-accumulator HMMA: C/D are 2 b32 regs holding 4 halves
__device__ __forceinline__ void mma16816_f16(uint32_t* c, const uint32_t* a,
                                             uint32_t b0, uint32_t b1) {
    asm volatile(
        "mma.sync.aligned.m16n8k16.row.col.f16.f16.f16.f16 "
        "{%0,%1}, {%2,%3,%4,%5}, {%6,%7}, {%0,%1};"
        : "+r"(c[0]), "+r"(c[1])
        : "r"(a[0]), "r"(a[1]), "r"(a[2]), "r"(a[3]), "r"(b0), "r"(b1));
}

// ------------------------------ prep kernels -------------------------------
__global__ void convert_x_kernel(const float* __restrict__ x) {
    size_t i = (size_t)blockIdx.x * blockDim.x + threadIdx.x; // 8 elems each
    const float4* X4 = reinterpret_cast<const float4*>(x);
    float4 a = X4[2 * i];
    float4 b = X4[2 * i + 1];
    __half2 h0 = __floats2half2_rn(a.x, a.y);
    __half2 h1 = __floats2half2_rn(a.z, a.w);
    __half2 h2 = __floats2half2_rn(b.x, b.y);
    __half2 h3 = __floats2half2_rn(b.z, b.w);
    uint4 o;
    o.x = *reinterpret_cast<uint32_t*>(&h0);
    o.y = *reinterpret_cast<uint32_t*>(&h1);
    o.z = *reinterpret_cast<uint32_t*>(&h2);
    o.w = *reinterpret_cast<uint32_t*>(&h3);
    reinterpret_cast<uint4*>(g_Xh)[i] = o;
}

__global__ void quantize_w_kernel(const float* __restrict__ W) {
    const int row = blockIdx.x;
    const int tid = threadIdx.x;
    const float* wr = W + (size_t)row * K_TOT;

    const int base = tid * 8;                        // 256 * 8 = 2048
    float4 a = *reinterpret_cast<const float4*>(wr + base);
    float4 b = *reinterpret_cast<const float4*>(wr + base + 4);
    float s = fabsf(a.x) + fabsf(a.y) + fabsf(a.z) + fabsf(a.w) +
              fabsf(b.x) + fabsf(b.y) + fabsf(b.z) + fabsf(b.w);
    #pragma unroll
    for (int o = 16; o; o >>= 1) s += __shfl_xor_sync(0xFFFFFFFFu, s, o);

    __shared__ float warp_s[8];
    __shared__ float s_scale;
    if ((tid & 31) == 0) warp_s[tid >> 5] = s;
    __syncthreads();
    if (tid == 0) {
        float t = 0.f;
        #pragma unroll
        for (int i = 0; i < 8; i++) t += warp_s[i];
        float sc = t * (1.0f / 2048.0f);
        if (sc < 1e-5f) sc = 1e-5f;
        g_scale[row] = sc;
        s_scale = sc;
    }
    __syncthreads();
    const float sc = s_scale;

    float v[8] = {a.x, a.y, a.z, a.w, b.x, b.y, b.z, b.w};
    __half q[8];
    #pragma unroll
    for (int i = 0; i < 8; i++) {
        float t = rintf(v[i] / sc);              // matches jnp.round
        t = fmaxf(-1.f, fminf(1.f, t));
        q[i] = __float2half_rn(t);
    }
    *reinterpret_cast<uint4*>(g_Wq + (size_t)row * K_TOT + base) =
        *reinterpret_cast<uint4*>(q);
}

// ------------------------------ GEMM kernel --------------------------------
__global__ void __launch_bounds__(256, 2)
bitlinear_gemm(float* __restrict__ out) {
    extern __shared__ char smem[];
    const uint32_t sbase = smem_u32(smem);
    const int tid    = threadIdx.x;
    const int wid    = tid >> 5;
    const int lane   = tid & 31;
    const int warp_m = wid & 1;       // 2 warps along M (64 each)
    const int warp_n = wid >> 1;      // 4 warps along N (32 each)
    const int m0 = blockIdx.y * BM;
    const int n0 = blockIdx.x * BN;

    const __half* Ag = g_Xh + (size_t)m0 * K_TOT;
    const __half* Bg = g_Wq + (size_t)n0 * K_TOT;

    // copy mapping: tile = 128 rows x 8 segs(16B) = 1024 segs; 4 per thread
    auto issue_copy = [&](int stage, int chunk) {
        const int k0 = chunk * BK;
        uint32_t da = sbase + SMEM_A_OFF(stage);
        uint32_t db = sbase + SMEM_B_OFF(stage);
        #pragma unroll
        for (int j = 0; j < 4; j++) {
            int s = tid + 256 * j;
            int row = s >> 3, sg = s & 7;
            uint32_t off = row * SROWB + sg * 16;
            cp_async16(da + off, Ag + (size_t)row * K_TOT + k0 + sg * 8);
            cp_async16(db + off, Bg + (size_t)row * K_TOT + k0 + sg * 8);
        }
    };

    // ldmatrix per-thread address components
    const int aRow = warp_m * 64 + (lane & 15);        // + mt*16
    const int aCol = (lane >> 4) * 8;                  // + ks*16
    const int g    = lane >> 3;
    const int bRow = warp_n * 32 + ((g >> 1) << 3) + (lane & 7);  // + nt*16
    const int bCol = (g & 1) * 8;                      // + ks*16

    float acc[4][4][4];          // fp32 master accumulators
    uint32_t hacc[4][4][2];      // fp16 span accumulators (4 halves each)
    #pragma unroll
    for (int i = 0; i < 4; i++)
        #pragma unroll
        for (int j = 0; j < 4; j++) {
            #pragma unroll
            for (int t = 0; t < 4; t++) acc[i][j][t] = 0.f;
            hacc[i][j][0] = 0u; hacc[i][j][1] = 0u;
        }

    // prologue: stages 0..1
    #pragma unroll
    for (int s = 0; s < STAGES - 1; s++) {
        issue_copy(s, s);
        asm volatile("cp.async.commit_group;");
    }

    for (int c = 0; c < NUM_CHUNKS; c++) {
        asm volatile("cp.async.wait_group %0;" :: "n"(STAGES - 2));
        __syncthreads();

        const int nc = c + STAGES - 1;
        if (nc < NUM_CHUNKS) issue_copy(nc % STAGES, nc);
        asm volatile("cp.async.commit_group;");

        const int st = c % STAGES;
        const uint32_t sa = sbase + SMEM_A_OFF(st);
        const uint32_t sb = sbase + SMEM_B_OFF(st);

        #pragma unroll
        for (int ks = 0; ks < 4; ks++) {
            uint32_t af[4][4];
            #pragma unroll
            for (int mt = 0; mt < 4; mt++)
                ldsm_x4(sa + (aRow + mt * 16) * SROWB + (aCol + ks * 16) * 2,
                        af[mt]);
            uint32_t bf[2][4];
            #pragma unroll
            for (int nt = 0; nt < 2; nt++)
                ldsm_x4(sb + (bRow + nt * 16) * SROWB + (bCol + ks * 16) * 2,
                        bf[nt]);
            #pragma unroll
            for (int mi = 0; mi < 4; mi++)
                #pragma unroll
                for (int ni = 0; ni < 4; ni++)
                    mma16816_f16(hacc[mi][ni], af[mi],
                                 bf[ni >> 1][(ni & 1) * 2],
                                 bf[ni >> 1][(ni & 1) * 2 + 1]);
        }

        // promote fp16 span accumulators -> fp32 every 2 chunks (K=128)
        if (c & 1) {
            #pragma unroll
            for (int mi = 0; mi < 4; mi++)
                #pragma unroll
                for (int ni = 0; ni < 4; ni++) {
                    float2 l0 = __half22float2(
                        *reinterpret_cast<__half2*>(&hacc[mi][ni][0]));
                    float2 l1 = __half22float2(
                        *reinterpret_cast<__half2*>(&hacc[mi][ni][1]));
                    acc[mi][ni][0] += l0.x;
                    acc[mi][ni][1] += l0.y;
                    acc[mi][ni][2] += l1.x;
                    acc[mi][ni][3] += l1.y;
                    hacc[mi][ni][0] = 0u;
                    hacc[mi][ni][1] = 0u;
                }
        }
    }

    // ---------------- epilogue: scale by g_scale[n], store fp32 ------------
    const int q = lane >> 2;          // row-in-8
    const int t = lane & 3;           // col-pair
    #pragma unroll
    for (int ni = 0; ni < 4; ni++) {
        const int n = n0 + warp_n * 32 + ni * 8 + t * 2;
        const float2 sc = *reinterpret_cast<const float2*>(&g_scale[n]);
        #pragma unroll
        for (int mi = 0; mi < 4; mi++) {
            const int m = m0 + warp_m * 64 + mi * 16 + q;
            float2 v0 = make_float2(acc[mi][ni][0] * sc.x, acc[mi][ni][1] * sc.y);
            float2 v1 = make_float2(acc[mi][ni][2] * sc.x, acc[mi][ni][3] * sc.y);
            *reinterpret_cast<float2*>(out + (size_t)m * N_TOT + n) = v0;
            *reinterpret_cast<float2*>(out + (size_t)(m + 8) * N_TOT + n) = v1;
        }
    }
}

// ------------------------------ launch -------------------------------------
extern "C" void kernel_launch(void* const* d_in, const int* in_sizes, int n_in,
                              void* d_out, int out_size) {
    const float* x = (const float*)d_in[0];      // [4,2048,2048]
    const float* w = (const float*)d_in[1];      // [8192,2048]
    float* out = (float*)d_out;                  // [4,2048,8192]

    cudaFuncSetAttribute(bitlinear_gemm,
                         cudaFuncAttributeMaxDynamicSharedMemorySize,
                         SMEM_TOTAL);

    convert_x_kernel<<<(M_TOT * K_TOT) / (256 * 8), 256>>>(x);
    quantize_w_kernel<<<N_TOT, 256>>>(w);

    dim3 grid(N_TOT / BN, M_TOT / BM);
    bitlinear_gemm<<<grid, 256, SMEM_TOTAL>>>(out);
}

// round 11
// speedup vs baseline: 4.9231x; 1.1010x over previous
#include <cuda_runtime.h>
#include <cuda_fp16.h>
#include <cstdint>

// ---------------------------------------------------------------------------
// BitLinear: out[m,n] = scale[n] * sum_k xh[m,k] * wq[n,k]
//   xh  = fp16(x)                  [8192, 2048]
//   wq  = ternary {-1,0,1} fp16    [8192, 2048]
//   out = fp32                     [8192, 8192]
//
// GEMM: mma.sync.m16n8k16.f32 (measured HW ceiling ~385 TF/s on sm_103
// legacy tensor path), CTA 128x128, 8 warps (64x32), BK=64, 3-stage
// cp.async, 2 CTAs/SM.  Prep (W quantize + x fp16 convert) fused into ONE
// launch so both memory-bound passes overlap.
// ---------------------------------------------------------------------------

#define M_TOT 8192
#define N_TOT 8192
#define K_TOT 2048

#define BM 128
#define BN 128
#define BK 64
#define STAGES 3
#define NUM_CHUNKS (K_TOT / BK)      // 32

// smem row: 64 halves + 8 pad = 72 halves = 144 bytes
#define SROWB 144
#define STILE_BYTES (BM * SROWB)     // 18432
#define SMEM_A_OFF(s) ((s) * STILE_BYTES)
#define SMEM_B_OFF(s) (STAGES * STILE_BYTES + (s) * STILE_BYTES)
#define SMEM_TOTAL (2 * STAGES * STILE_BYTES)   // 110592

__device__ __half g_Xh[(size_t)M_TOT * K_TOT];
__device__ __half g_Wq[(size_t)N_TOT * K_TOT];
__device__ float  g_scale[N_TOT];

// ------------------------------ helpers ------------------------------------
__device__ __forceinline__ uint32_t smem_u32(const void* p) {
    uint32_t a;
    asm("{ .reg .u64 t; cvta.to.shared.u64 t, %1; cvt.u32.u64 %0, t; }"
        : "=r"(a) : "l"(p));
    return a;
}

__device__ __forceinline__ void cp_async16(uint32_t dst, const void* src) {
    asm volatile("cp.async.cg.shared.global [%0], [%1], 16;"
                 :: "r"(dst), "l"(src));
}

__device__ __forceinline__ void ldsm_x4(uint32_t addr, uint32_t* r) {
    asm volatile("ldmatrix.sync.aligned.m8n8.x4.shared.b16 {%0,%1,%2,%3}, [%4];"
                 : "=r"(r[0]), "=r"(r[1]), "=r"(r[2]), "=r"(r[3]) : "r"(addr));
}

__device__ __forceinline__ void mma16816(float* c, const uint32_t* a,
                                         uint32_t b0, uint32_t b1) {
    asm volatile(
        "mma.sync.aligned.m16n8k16.row.col.f32.f16.f16.f32 "
        "{%0,%1,%2,%3}, {%4,%5,%6,%7}, {%8,%9}, {%0,%1,%2,%3};"
        : "+f"(c[0]), "+f"(c[1]), "+f"(c[2]), "+f"(c[3])
        : "r"(a[0]), "r"(a[1]), "r"(a[2]), "r"(a[3]), "r"(b0), "r"(b1));
}

// ------------------------------ fused prep kernel --------------------------
// blocks [0, 8192): quantize W row b  -> g_Wq, g_scale
// blocks [8192, 16384): convert x slice (b-8192) -> g_Xh (2048 elems each)
__global__ void prep_kernel(const float* __restrict__ x,
                            const float* __restrict__ W) {
    const int b   = blockIdx.x;
    const int tid = threadIdx.x;

    if (b < N_TOT) {
        // ---- quantize one weight row ----
        const float* wr = W + (size_t)b * K_TOT;
        const int base = tid * 8;                    // 256 * 8 = 2048
        float4 a = *reinterpret_cast<const float4*>(wr + base);
        float4 c = *reinterpret_cast<const float4*>(wr + base + 4);
        float s = fabsf(a.x) + fabsf(a.y) + fabsf(a.z) + fabsf(a.w) +
                  fabsf(c.x) + fabsf(c.y) + fabsf(c.z) + fabsf(c.w);
        #pragma unroll
        for (int o = 16; o; o >>= 1) s += __shfl_xor_sync(0xFFFFFFFFu, s, o);

        __shared__ float warp_s[8];
        __shared__ float s_scale;
        if ((tid & 31) == 0) warp_s[tid >> 5] = s;
        __syncthreads();
        if (tid == 0) {
            float t = 0.f;
            #pragma unroll
            for (int i = 0; i < 8; i++) t += warp_s[i];
            float sc = t * (1.0f / 2048.0f);
            if (sc < 1e-5f) sc = 1e-5f;
            g_scale[b] = sc;
            s_scale = sc;
        }
        __syncthreads();
        const float sc = s_scale;

        float v[8] = {a.x, a.y, a.z, a.w, c.x, c.y, c.z, c.w};
        __half q[8];
        #pragma unroll
        for (int i = 0; i < 8; i++) {
            float t = rintf(v[i] / sc);          // matches jnp.round
            t = fmaxf(-1.f, fminf(1.f, t));
            q[i] = __float2half_rn(t);
        }
        *reinterpret_cast<uint4*>(g_Wq + (size_t)b * K_TOT + base) =
            *reinterpret_cast<uint4*>(q);
    } else {
        // ---- convert one 2048-element slice of x to fp16 ----
        size_t i = (size_t)(b - N_TOT) * 256 + tid;  // uint4 index (8 elems)
        const float4* X4 = reinterpret_cast<const float4*>(x);
        float4 a = X4[2 * i];
        float4 c = X4[2 * i + 1];
        __half2 h0 = __floats2half2_rn(a.x, a.y);
        __half2 h1 = __floats2half2_rn(a.z, a.w);
        __half2 h2 = __floats2half2_rn(c.x, c.y);
        __half2 h3 = __floats2half2_rn(c.z, c.w);
        uint4 o;
        o.x = *reinterpret_cast<uint32_t*>(&h0);
        o.y = *reinterpret_cast<uint32_t*>(&h1);
        o.z = *reinterpret_cast<uint32_t*>(&h2);
        o.w = *reinterpret_cast<uint32_t*>(&h3);
        reinterpret_cast<uint4*>(g_Xh)[i] = o;
    }
}

// ------------------------------ GEMM kernel --------------------------------
__global__ void __launch_bounds__(256, 2)
bitlinear_gemm(float* __restrict__ out) {
    extern __shared__ char smem[];
    const uint32_t sbase = smem_u32(smem);
    const int tid    = threadIdx.x;
    const int wid    = tid >> 5;
    const int lane   = tid & 31;
    const int warp_m = wid & 1;       // 2 warps along M (64 each)
    const int warp_n = wid >> 1;      // 4 warps along N (32 each)
    const int m0 = blockIdx.y * BM;
    const int n0 = blockIdx.x * BN;

    const __half* Ag = g_Xh + (size_t)m0 * K_TOT;
    const __half* Bg = g_Wq + (size_t)n0 * K_TOT;

    // copy mapping: tile = 128 rows x 8 segs(16B) = 1024 segs; 4 per thread
    auto issue_copy = [&](int stage, int chunk) {
        const int k0 = chunk * BK;
        uint32_t da = sbase + SMEM_A_OFF(stage);
        uint32_t db = sbase + SMEM_B_OFF(stage);
        #pragma unroll
        for (int j = 0; j < 4; j++) {
            int s = tid + 256 * j;
            int row = s >> 3, sg = s & 7;
            uint32_t off = row * SROWB + sg * 16;
            cp_async16(da + off, Ag + (size_t)row * K_TOT + k0 + sg * 8);
            cp_async16(db + off, Bg + (size_t)row * K_TOT + k0 + sg * 8);
        }
    };

    // ldmatrix per-thread address components
    const int aRow = warp_m * 64 + (lane & 15);        // + mt*16
    const int aCol = (lane >> 4) * 8;                  // + ks*16
    const int g    = lane >> 3;
    const int bRow = warp_n * 32 + ((g >> 1) << 3) + (lane & 7);  // + nt*16
    const int bCol = (g & 1) * 8;                      // + ks*16

    float acc[4][4][4];
    #pragma unroll
    for (int i = 0; i < 4; i++)
        #pragma unroll
        for (int j = 0; j < 4; j++)
            #pragma unroll
            for (int t = 0; t < 4; t++) acc[i][j][t] = 0.f;

    // prologue: stages 0..1
    #pragma unroll
    for (int s = 0; s < STAGES - 1; s++) {
        issue_copy(s, s);
        asm volatile("cp.async.commit_group;");
    }

    for (int c = 0; c < NUM_CHUNKS; c++) {
        asm volatile("cp.async.wait_group %0;" :: "n"(STAGES - 2));
        __syncthreads();

        const int nc = c + STAGES - 1;
        if (nc < NUM_CHUNKS) issue_copy(nc % STAGES, nc);
        asm volatile("cp.async.commit_group;");

        const int st = c % STAGES;
        const uint32_t sa = sbase + SMEM_A_OFF(st);
        const uint32_t sb = sbase + SMEM_B_OFF(st);

        #pragma unroll
        for (int ks = 0; ks < 4; ks++) {
            uint32_t af[4][4];
            #pragma unroll
            for (int mt = 0; mt < 4; mt++)
                ldsm_x4(sa + (aRow + mt * 16) * SROWB + (aCol + ks * 16) * 2,
                        af[mt]);
            uint32_t bf[2][4];
            #pragma unroll
            for (int nt = 0; nt < 2; nt++)
                ldsm_x4(sb + (bRow + nt * 16) * SROWB + (bCol + ks * 16) * 2,
                        bf[nt]);
            #pragma unroll
            for (int mi = 0; mi < 4; mi++)
                #pragma unroll
                for (int ni = 0; ni < 4; ni++)
                    mma16816(acc[mi][ni], af[mi],
                             bf[ni >> 1][(ni & 1) * 2],
                             bf[ni >> 1][(ni & 1) * 2 + 1]);
        }
    }

    // ---------------- epilogue: scale by g_scale[n], store fp32 ------------
    const int q = lane >> 2;          // row-in-8
    const int t = lane & 3;           // col-pair
    #pragma unroll
    for (int ni = 0; ni < 4; ni++) {
        const int n = n0 + warp_n * 32 + ni * 8 + t * 2;
        const float2 sc = *reinterpret_cast<const float2*>(&g_scale[n]);
        #pragma unroll
        for (int mi = 0; mi < 4; mi++) {
            const int m = m0 + warp_m * 64 + mi * 16 + q;
            float2 v0 = make_float2(acc[mi][ni][0] * sc.x, acc[mi][ni][1] * sc.y);
            float2 v1 = make_float2(acc[mi][ni][2] * sc.x, acc[mi][ni][3] * sc.y);
            *reinterpret_cast<float2*>(out + (size_t)m * N_TOT + n) = v0;
            *reinterpret_cast<float2*>(out + (size_t)(m + 8) * N_TOT + n) = v1;
        }
    }
}

// ------------------------------ launch -------------------------------------
extern "C" void kernel_launch(void* const* d_in, const int* in_sizes, int n_in,
                              void* d_out, int out_size) {
    const float* x = (const float*)d_in[0];      // [4,2048,2048]
    const float* w = (const float*)d_in[1];      // [8192,2048]
    float* out = (float*)d_out;                  // [4,2048,8192]

    cudaFuncSetAttribute(bitlinear_gemm,
                         cudaFuncAttributeMaxDynamicSharedMemorySize,
                         SMEM_TOTAL);

    // fused prep: 8192 W-row blocks + 8192 x-convert blocks, one launch
    prep_kernel<<<N_TOT + (M_TOT * K_TOT) / (256 * 8), 256>>>(x, w);

    dim3 grid(N_TOT / BN, M_TOT / BM);
    bitlinear_gemm<<<grid, 256, SMEM_TOTAL>>>(out);
}